// round 17
// baseline (speedup 1.0000x reference)
#include <cuda_runtime.h>
#include <cuda_fp16.h>
#include <cstdint>

// ---------------- problem constants ----------------
#define BATCH  16384
#define NFEAT  16
#define MTOT   4844
#define KPAD   4864          // pad monomial = 1, pad W = 0
#define KSTAGE 64
#define TSTAGE 76            // stages per tile
#define NTILES 256           // 16384 / 64
#define OUTD   256
#define BM     64
#define NTHR   256           // 8 warps: 2 (M32) x 4 (N64)
#define NCTA   304           // = 2 x 152 SMs; 304*64 = 256*76 exactly
#define UNITS  64            // stage-units per CTA
#define EHSTR  162

// SMEM (bytes): XOR-swizzled 128B rows; A 3-deep, B 2-deep
#define A_BUFSZ 8192
#define B_BUFSZ 32768
#define A_OFF   0
#define B_OFF   (3 * A_BUFSZ)                  // 24576
#define E_OFF   (B_OFF + 2 * B_BUFSZ)          // 90112
#define SMEM_REQ (E_OFF + BM * EHSTR * 2)      // 110848 (x2 CTAs fits)

// ---------------- device globals ----------------
__device__ __align__(16) __half   g_Wh[OUTD * KPAD];
__device__ __align__(16) uint32_t g_TBL[KPAD];
__device__ uint32_t g_PAIRT[136];

__device__ __forceinline__ int pair_rank(int a, int b) {
    return a * 16 - (a * (a - 1)) / 2 + (b - a);
}

__global__ void prep_all(const float* __restrict__ W) {
    int idx = blockIdx.x * blockDim.x + threadIdx.x;
    if (idx < 136) {
        int r = idx, a = 0;
        while (r >= 16 - a) { r -= 16 - a; a++; }
        g_PAIRT[idx] = (uint32_t)a | ((uint32_t)(a + r) << 8);
    }
    if (idx < KPAD) {
        int m = idx;
        uint32_t e1 = 0, e2 = 0;
        if (m < 16) {
            e1 = 1 + m; e2 = 0;
        } else if (m < 152) {
            e1 = 17 + (m - 16); e2 = 0;
        } else if (m < 968) {
            int r = m - 152, a = 0;
            while (true) { int k = 16 - a; int t2 = k * (k + 1) / 2; if (r < t2) break; r -= t2; a++; }
            int b = a;
            while (r >= 16 - b) { r -= 16 - b; b++; }
            int c = b + r;
            e1 = 1 + a; e2 = 17 + pair_rank(b, c);
        } else if (m < MTOT) {
            int r = m - 968, a = 0;
            while (true) { int k = 16 - a; int t3 = k * (k + 1) * (k + 2) / 6; if (r < t3) break; r -= t3; a++; }
            int b = a;
            while (true) { int k = 16 - b; int t2 = k * (k + 1) / 2; if (r < t2) break; r -= t2; b++; }
            int c = b;
            while (r >= 16 - c) { r -= 16 - c; c++; }
            int d = c + r;
            e1 = 17 + pair_rank(a, b); e2 = 17 + pair_rank(c, d);
        } else {
            e1 = 0; e2 = 0;
        }
        g_TBL[m] = e1 | (e2 << 16);
    }
    if (idx < OUTD * KPAD) {
        int n = idx / KPAD, k = idx - n * KPAD;
        float w = (k < MTOT) ? W[(size_t)n * MTOT + k] : 0.0f;
        g_Wh[idx] = __float2half_rn(w);
    }
}

// ---------------- PTX helpers ----------------
__device__ __forceinline__ uint32_t smem_u32(const void* p) {
    uint32_t a;
    asm("{ .reg .u64 t; cvta.to.shared.u64 t, %1; cvt.u32.u64 %0, t; }" : "=r"(a) : "l"(p));
    return a;
}
__device__ __forceinline__ void cp_async16(uint32_t dst, const void* src) {
    asm volatile("cp.async.cg.shared.global [%0], [%1], 16;" :: "r"(dst), "l"(src) : "memory");
}
__device__ __forceinline__ void ldsm_x4(uint32_t (&r)[4], uint32_t addr) {
    asm volatile("ldmatrix.sync.aligned.m8n8.x4.shared.b16 {%0,%1,%2,%3}, [%4];"
                 : "=r"(r[0]), "=r"(r[1]), "=r"(r[2]), "=r"(r[3]) : "r"(addr));
}
__device__ __forceinline__ void mma16816(float (&c)[4], const uint32_t (&a)[4],
                                         uint32_t b0, uint32_t b1) {
    asm volatile(
        "mma.sync.aligned.m16n8k16.row.col.f32.f16.f16.f32 "
        "{%0,%1,%2,%3}, {%4,%5,%6,%7}, {%8,%9}, {%0,%1,%2,%3};"
        : "+f"(c[0]), "+f"(c[1]), "+f"(c[2]), "+f"(c[3])
        : "r"(a[0]), "r"(a[1]), "r"(a[2]), "r"(a[3]), "r"(b0), "r"(b1));
}
__device__ __forceinline__ void red_add_f32(float* p, float v) {
    asm volatile("red.global.add.f32 [%0], %1;" :: "l"(p), "f"(v) : "memory");
}

// ---------------- main kernel: stage-granular split-K, perfectly balanced ----------------
// 304 CTAs x 256 threads = exactly 2 CTAs on each of 152 SMs, 64 stage-units each.
// CTA c processes units [64c, 64c+64): at most 2 (tile, stage-range) segments.
// Partial results accumulated into out via RED.ADD (out pre-zeroed by memset).
__global__ void __launch_bounds__(NTHR, 2) taylor_main(
    const float* __restrict__ x,
    float* __restrict__ out)
{
    extern __shared__ char smem[];
    const uint32_t sbase = smem_u32(smem);
    __half* Eh = (__half*)(smem + E_OFF);

    const int tid  = threadIdx.x;
    const int wid  = tid >> 5;
    const int lane = tid & 31;
    const int wm   = wid & 1;
    const int wn   = wid >> 1;

    // gen assignment (tile-independent)
    const int grow = tid & 63;
    const int gkb  = (tid >> 6) << 4;
    const int gseg = gkb >> 3;
    const int grb  = grow & 7;
    const __half* Er = Eh + grow * EHSTR;
    const uint32_t gA0 = sbase + A_OFF + grow * 128 + (uint32_t)((gseg    ) ^ grb) * 16;
    const uint32_t gA1 = sbase + A_OFF + grow * 128 + (uint32_t)((gseg + 1) ^ grb) * 16;

    #define GEN_A(s_, bo_) do {                                                     \
        const int mb = (s_) * KSTAGE + gkb;                                         \
        uint32_t tt[16];                                                            \
        *(uint4*)&tt[0]  = *(const uint4*)&g_TBL[mb];                               \
        *(uint4*)&tt[4]  = *(const uint4*)&g_TBL[mb + 4];                           \
        *(uint4*)&tt[8]  = *(const uint4*)&g_TBL[mb + 8];                           \
        *(uint4*)&tt[12] = *(const uint4*)&g_TBL[mb + 12];                          \
        uint32_t hh[8];                                                             \
        _Pragma("unroll")                                                           \
        for (int q = 0; q < 8; ++q) {                                               \
            uint32_t t0 = tt[2 * q], t1 = tt[2 * q + 1];                            \
            __half p0 = __hmul(Er[t0 & 0xffff], Er[t0 >> 16]);                      \
            __half p1 = __hmul(Er[t1 & 0xffff], Er[t1 >> 16]);                      \
            hh[q] = (uint32_t)__half_as_ushort(p0) |                                \
                    ((uint32_t)__half_as_ushort(p1) << 16);                         \
        }                                                                           \
        asm volatile("st.shared.v4.b32 [%0], {%1,%2,%3,%4};"                        \
                     :: "r"(gA0 + (bo_)), "r"(hh[0]), "r"(hh[1]), "r"(hh[2]), "r"(hh[3]) : "memory"); \
        asm volatile("st.shared.v4.b32 [%0], {%1,%2,%3,%4};"                        \
                     :: "r"(gA1 + (bo_)), "r"(hh[4]), "r"(hh[5]), "r"(hh[6]), "r"(hh[7]) : "memory"); \
    } while (0)

    #define LOAD_B(s_, bo_) do {                                                    \
        _Pragma("unroll")                                                           \
        for (int i2 = 0; i2 < 8; ++i2) {                                            \
            int c2 = tid + i2 * NTHR;                                               \
            int row = c2 >> 3, seg = c2 & 7;                                        \
            const __half* src = g_Wh + (size_t)row * KPAD + (s_) * KSTAGE + seg * 8;\
            cp_async16(sbase + B_OFF + (bo_) + row * 128 +                          \
                       (uint32_t)(seg ^ (row & 7)) * 16, src);                      \
        }                                                                           \
        asm volatile("cp.async.commit_group;" ::: "memory");                        \
    } while (0)

    // ldsm lane addressing
    const int ra   = wm * 32 + (lane & 15);
    const int arb  = ra & 7;
    const int alog = lane >> 4;
    const uint32_t aBase = sbase + A_OFF + ra * 128;
    const int bq    = lane >> 3;
    const int rbrow = wn * 64 + ((bq >> 1) << 3) + (lane & 7);
    const int brb   = rbrow & 7;
    const int blog  = bq & 1;
    const uint32_t bBase = sbase + B_OFF + rbrow * 128;

    int u = blockIdx.x * UNITS;
    int remaining = UNITS;

    while (remaining > 0) {
        const int tile = u / TSTAGE;
        const int sb   = u - tile * TSTAGE;
        const int ns   = min(TSTAGE - sb, remaining);
        const int b0   = tile * BM;

        // ---- segment prologue: build Eh for this tile ----
        __syncthreads();   // prior segment fully done with smem
        {
            float* Tf = (float*)(smem + A_OFF);
            #pragma unroll
            for (int i = 0; i < (BM * NFEAT) / NTHR; ++i) {
                int q = tid + i * NTHR;
                int row = q >> 4, f = q & 15;
                float t = tanhf(x[(size_t)(b0 + row) * NFEAT + f]);
                Tf[row * 17 + f] = t;
                Eh[row * EHSTR + 1 + f] = __float2half_rn(t);
            }
            if (tid < BM) Eh[tid * EHSTR] = __float2half_rn(1.0f);
            __syncthreads();
            #pragma unroll
            for (int i = 0; i < (136 * BM) / NTHR; ++i) {
                int q = tid + i * NTHR;
                int row = q & 63, p = q >> 6;
                uint32_t pr = g_PAIRT[p];
                Eh[row * EHSTR + 17 + p] = __float2half_rn(
                    Tf[row * 17 + (pr & 255)] * Tf[row * 17 + ((pr >> 8) & 255)]);
            }
            __syncthreads();
        }

        // ---- pipeline prologue ----
        GEN_A(sb, 0);
        if (ns > 1) GEN_A(sb + 1, A_BUFSZ);
        LOAD_B(sb, 0);

        float acc[2][8][4];
        #pragma unroll
        for (int i = 0; i < 2; ++i)
            #pragma unroll
            for (int j = 0; j < 8; ++j)
                #pragma unroll
                for (int q = 0; q < 4; ++q) acc[i][j][q] = 0.0f;

        int bufA = 0, bufA2 = 2 * A_BUFSZ;

        for (int i = 0; i < ns; ++i) {
            asm volatile("cp.async.wait_group 0;" ::: "memory");
            __syncthreads();

            if (i + 1 < ns) LOAD_B(sb + i + 1, ((i + 1) & 1) * B_BUFSZ);
            if (i + 2 < ns) GEN_A(sb + i + 2, bufA2);

            const uint32_t aB = aBase + bufA;
            const uint32_t bB = bBase + (i & 1) * B_BUFSZ;
            #pragma unroll
            for (int kf = 0; kf < 4; ++kf) {
                uint32_t a[2][4];
                const uint32_t aoff = (uint32_t)((alog + 2 * kf) ^ arb) * 16;
                ldsm_x4(a[0], aB + aoff);
                ldsm_x4(a[1], aB + aoff + 16 * 128);
                const uint32_t boff = (uint32_t)((blog + 2 * kf) ^ brb) * 16;
                #pragma unroll
                for (int nb = 0; nb < 4; ++nb) {
                    uint32_t b[4];
                    ldsm_x4(b, bB + nb * (16 * 128) + boff);
                    mma16816(acc[0][nb * 2 + 0], a[0], b[0], b[1]);
                    mma16816(acc[0][nb * 2 + 1], a[0], b[2], b[3]);
                    mma16816(acc[1][nb * 2 + 0], a[1], b[0], b[1]);
                    mma16816(acc[1][nb * 2 + 1], a[1], b[2], b[3]);
                }
            }

            bufA += A_BUFSZ;  if (bufA  == 3 * A_BUFSZ) bufA  = 0;
            bufA2 += A_BUFSZ; if (bufA2 == 3 * A_BUFSZ) bufA2 = 0;
        }

        // ---- segment epilogue: accumulate partial into out ----
        {
            const int rbase = b0 + wm * 32 + (lane >> 2);
            const int cbase = wn * 64 + (lane & 3) * 2;
            #pragma unroll
            for (int mf = 0; mf < 2; ++mf) {
                #pragma unroll
                for (int nf = 0; nf < 8; ++nf) {
                    const int col = cbase + nf * 8;
                    const int r0 = rbase + mf * 16;
                    float* p0 = out + (size_t)r0 * OUTD + col;
                    float* p1 = out + (size_t)(r0 + 8) * OUTD + col;
                    red_add_f32(p0,     acc[mf][nf][0]);
                    red_add_f32(p0 + 1, acc[mf][nf][1]);
                    red_add_f32(p1,     acc[mf][nf][2]);
                    red_add_f32(p1 + 1, acc[mf][nf][3]);
                }
            }
        }

        u += ns;
        remaining -= ns;
    }
    #undef GEN_A
    #undef LOAD_B
}

// ---------------- final: out = relu(out + bias) ----------------
__global__ void bias_relu(float* __restrict__ out, const float* __restrict__ bias) {
    int idx = blockIdx.x * blockDim.x + threadIdx.x;      // over float4s
    float4 v = reinterpret_cast<float4*>(out)[idx];
    int col = (idx * 4) & (OUTD - 1);
    v.x = fmaxf(v.x + __ldg(&bias[col + 0]), 0.0f);
    v.y = fmaxf(v.y + __ldg(&bias[col + 1]), 0.0f);
    v.z = fmaxf(v.z + __ldg(&bias[col + 2]), 0.0f);
    v.w = fmaxf(v.w + __ldg(&bias[col + 3]), 0.0f);
    reinterpret_cast<float4*>(out)[idx] = v;
}

// ---------------- launch ----------------
extern "C" void kernel_launch(void* const* d_in, const int* in_sizes, int n_in,
                              void* d_out, int out_size) {
    const float* x = (const float*)d_in[0];
    const float* W = (const float*)d_in[1];
    const float* b = (const float*)d_in[2];
    float* out = (float*)d_out;

    cudaFuncSetAttribute(taylor_main, cudaFuncAttributeMaxDynamicSharedMemorySize, SMEM_REQ);

    prep_all<<<(OUTD * KPAD + 255) / 256, 256>>>(W);
    cudaMemsetAsync(out, 0, (size_t)BATCH * OUTD * sizeof(float));
    taylor_main<<<NCTA, NTHR, SMEM_REQ>>>(x, out);
    bias_relu<<<(BATCH * OUTD / 4 + 255) / 256, 256>>>(out, b);
}